// round 14
// baseline (speedup 1.0000x reference)
#include <cuda_runtime.h>
#include <cuda_fp16.h>
#include <cstdint>

#define LENGTH   262144
#define NFFT     2048
#define HOP      512
#define BATCH    16
#define FRAMES   513
#define NCOLS    (BATCH * FRAMES)      // 8208
#define NPAD     8448                  // 66 * 128
#define KPE      320                   // even phases: 257 live + pad (5 chunks)
#define KPO      576                   // odd phases: 513 live + pad (9 chunks)
#define NCHE     5
#define NCHO     9
#define KC       64
#define MT2      128
#define NT2      128
#define A_BYTES  (MT2 * 128)
#define B_BYTES  (NT2 * 128)
#define STAGE_BYTES (A_BYTES + B_BYTES) // 32768
#define STAGES   3
#define SMEM_TOTAL (STAGES * STAGE_BYTES) // 98304
#define NW_E     (4 * 256 * KPE)       // 327680
#define NW_O     (2 * 512 * KPO)       // 589824
#define WBLOCKS  ((NW_E + NW_O) / 256) // 3584

// even B phases: 0=Pe2p (k=4m), 1=Pe2m (k=4m+2), 2=Me2m (k=4m), 3=Me2p (k=4m+2)
__device__ __align__(16) __half g_We[NW_E];
__device__ __align__(16) __half g_Wo[NW_O];
__device__ __align__(16) __half g_Be[4 * NPAD * KPE];   // 21.6 MB
__device__ __align__(16) __half g_Bo[2 * NPAD * KPO];   // 19.5 MB

__device__ __forceinline__ uint32_t smem_u32(const void* p) {
    uint32_t a;
    asm("{ .reg .u64 t; cvta.to.shared.u64 t, %1; cvt.u32.u64 %0, t; }" : "=r"(a) : "l"(p));
    return a;
}
__device__ __forceinline__ void cpa(uint32_t dst, uint64_t gsrc) {
    asm volatile("cp.async.cg.shared.global [%0], [%1], 16;" :: "r"(dst), "l"(gsrc) : "memory");
}
__device__ __forceinline__ void ldsm4(uint32_t* r, uint32_t a) {
    asm volatile("ldmatrix.sync.aligned.m8n8.x4.shared.b16 {%0,%1,%2,%3}, [%4];"
        : "=r"(r[0]), "=r"(r[1]), "=r"(r[2]), "=r"(r[3]) : "r"(a));
}
__device__ __forceinline__ void mma16(float* c, const uint32_t* a, const uint32_t* b) {
    asm volatile("mma.sync.aligned.m16n8k16.row.col.f32.f16.f16.f32 "
        "{%0,%1,%2,%3}, {%4,%5,%6,%7}, {%8,%9}, {%0,%1,%2,%3};"
        : "+f"(c[0]), "+f"(c[1]), "+f"(c[2]), "+f"(c[3])
        : "r"(a[0]), "r"(a[1]), "r"(a[2]), "r"(a[3]), "r"(b[0]), "r"(b[1]));
}
__device__ __forceinline__ float xrefl(const float* xb, int i) {
    if (i < 0) i = -i;
    else if (i >= LENGTH) i = 2 * LENGTH - 2 - i;
    return xb[i];
}

// ---- fused prep: blocks [0, NPAD) build B; blocks [NPAD, NPAD+WBLOCKS) build W ----
__global__ __launch_bounds__(256) void prep_all(const float* __restrict__ x,
                                                float* __restrict__ out)
{
    const int tid = threadIdx.x;

    if (blockIdx.x >= NPAD) {
        // ---------- W builder ----------
        int idx = (blockIdx.x - NPAD) * 256 + tid;
        if (idx < NW_E) {
            int p = idx / (256 * KPE);
            int r = idx - p * (256 * KPE);
            int m = r / KPE;
            int n = r - m * KPE;
            float v = 0.f;
            if (n <= 256) {
                if (p == 0)      v = cospif((float)(m * n) / 256.0f);
                else if (p == 1) v = cospif((float)((2 * m + 1) * n) / 512.0f);
                else if (p == 2) v = sinpif((float)(m * n) / 256.0f);
                else             v = sinpif((float)((2 * m + 1) * n) / 512.0f);
            }
            g_We[idx] = __float2half_rn(v);
        } else {
            int r = idx - NW_E;
            if (r < NW_O) {
                int p = r / (512 * KPO);
                int q = r - p * (512 * KPO);
                int m = q / KPO;
                int n = q - m * KPO;
                float v = 0.f;
                if (n <= 512) {
                    float u = (float)((2 * m + 1) * n) / 1024.0f;
                    v = p ? sinpif(u) : cospif(u);
                }
                g_Wo[r] = __float2half_rn(v);
            }
        }
        return;
    }

    // ---------- B builder: one column per block ----------
    __shared__ __align__(16) float xs[2052];
    __shared__ float sPe[513];
    __shared__ float sMe[513];
    __shared__ float red[8];
    const int col = blockIdx.x;

    __half* be0 = g_Be + 0 * (size_t)NPAD * KPE + (size_t)col * KPE;
    __half* be1 = g_Be + 1 * (size_t)NPAD * KPE + (size_t)col * KPE;
    __half* be2 = g_Be + 2 * (size_t)NPAD * KPE + (size_t)col * KPE;
    __half* be3 = g_Be + 3 * (size_t)NPAD * KPE + (size_t)col * KPE;
    __half* bo0 = g_Bo + 0 * (size_t)NPAD * KPO + (size_t)col * KPO;
    __half* bo1 = g_Bo + 1 * (size_t)NPAD * KPO + (size_t)col * KPO;

    if (col >= NCOLS) {
        __half z = __float2half_rn(0.f);
        for (int n = tid; n < KPE; n += 256) { be0[n] = z; be1[n] = z; be2[n] = z; be3[n] = z; }
        for (int j = tid; j < KPO; j += 256) { bo0[j] = z; bo1[j] = z; }
        return;
    }

    const int b = col / FRAMES;
    const int t = col - b * FRAMES;
    const float* __restrict__ xb = x + (size_t)b * LENGTH;
    const int base = t * HOP - 1024;

    for (int u = tid; u < 513; u += 256) {
        int gi = base + u * 4;
        float4 v;
        if (gi >= 0 && gi + 3 < LENGTH) {
            v = *(const float4*)(xb + gi);
        } else {
            float* vv = (float*)&v;
            #pragma unroll
            for (int e = 0; e < 4; e++) vv[e] = xrefl(xb, gi + e);
        }
        *(float4*)&xs[u * 4] = v;
    }
    __syncthreads();

    float alt = 0.f;
    for (int j = tid; j < KPO; j += 256) {
        float vpo = 0.f, vmo = 0.f;
        if (j <= 512) {
            float winj = 0.5f - 0.5f * cospif((float)j / 1024.0f);
            float winp = 1.0f - winj;
            float xa  = xs[j];
            float xd  = xs[1024 + j];
            float xr2 = xs[2048 - j];
            float xr1 = xs[1024 - j];
            float qa = winj * (xa + xr2);
            float qb = winp * (xr1 + xd);
            float ma = winj * (xa - xr2);
            float mb = winp * (xr1 - xd);
            float h = (j == 0 || j == 512) ? 0.5f : 1.0f;
            float vpe = (qa + qb) * h;
            vpo = (qa - qb) * h;
            float vme = (ma - mb) * h;
            vmo = (ma + mb) * h;
            alt += (j & 1) ? -vpe : vpe;
            sPe[j] = vpe;
            sMe[j] = vme;
        }
        bo0[j] = __float2half_rn(vpo);
        bo1[j] = __float2half_rn(vmo);
    }
    __syncthreads();

    // second fold: even-bin B vectors, n = 0..256 (pad to 320)
    for (int n = tid; n < KPE; n += 256) {
        float p2p = 0.f, p2m = 0.f, m2m = 0.f, m2p = 0.f;
        if (n <= 256) {
            float a = sPe[n], c = sPe[512 - n];
            float d = sMe[n], e = sMe[512 - n];
            float h2 = (n == 256) ? 0.5f : 1.0f;
            p2p = (a + c) * h2;
            p2m = (a - c) * h2;
            m2m = (d - e) * h2;
            m2p = (d + e) * h2;
        }
        be0[n] = __float2half_rn(p2p);
        be1[n] = __float2half_rn(p2m);
        be2[n] = __float2half_rn(m2m);
        be3[n] = __float2half_rn(m2p);
    }

    #pragma unroll
    for (int off = 16; off > 0; off >>= 1)
        alt += __shfl_down_sync(0xFFFFFFFF, alt, off);
    if ((tid & 31) == 0) red[tid >> 5] = alt;
    __syncthreads();
    if (tid == 0) {
        float s = 0.f;
        #pragma unroll
        for (int w = 0; w < 8; w++) s += red[w];
        const size_t TOT = (size_t)BATCH * NFFT * FRAMES;
        size_t o = ((size_t)b * NFFT + 1024) * FRAMES + t;
        out[o] = s;
        out[TOT + o] = 0.f;
    }
}

// ---- unified GEMM: grid (66, 16); ty<8 even tiles (K=320), ty>=8 odd (K=576) ----
__global__ __launch_bounds__(256, 2) void stft_mma7(float* __restrict__ out)
{
    extern __shared__ __align__(128) char smem[];
    const uint32_t sb = smem_u32(smem);
    const int tid  = threadIdx.x;
    const int lane = tid & 31;
    const int wid  = tid >> 5;
    const int ct = blockIdx.x;
    const int ty = blockIdx.y;
    const int wm = wid & 1;
    const int wn = wid >> 1;

    int KP, NCHv, kbase, kstep;
    bool is_imag;
    const __half *Aptr, *Bptr;
    if (ty < 8) {
        int pe  = ty >> 1;
        int mr0 = (ty & 1) * 128;
        KP = KPE; NCHv = NCHE;
        Aptr = g_We + ((size_t)pe * 256 + mr0) * KPE;
        Bptr = g_Be + ((size_t)pe * NPAD + (size_t)ct * NT2) * KPE;
        is_imag = (pe >= 2);
        kbase = 4 * mr0 + ((pe & 1) ? 2 : 0);
        kstep = 4;
    } else {
        int po  = (ty - 8) >> 2;
        int mr0 = ((ty - 8) & 3) * 128;
        KP = KPO; NCHv = NCHO;
        Aptr = g_Wo + ((size_t)po * 512 + mr0) * KPO;
        Bptr = g_Bo + ((size_t)po * NPAD + (size_t)ct * NT2) * KPO;
        is_imag = (po == 1);
        kbase = 2 * mr0 + 1;
        kstep = 2;
    }

    uint32_t dstT[4]; uint64_t srcT[4];
    #pragma unroll
    for (int r = 0; r < 4; r++) {
        int idx = tid + r * 256;
        int row = idx >> 3, kg = idx & 7;
        dstT[r] = (uint32_t)(row * 128 + ((kg ^ (row & 7)) << 4));
        srcT[r] = (uint64_t)row * (KP * 2) + (uint64_t)kg * 16;
    }
    uint64_t gA, gB;
    asm("cvta.to.global.u64 %0, %1;" : "=l"(gA) : "l"(Aptr));
    asm("cvta.to.global.u64 %0, %1;" : "=l"(gB) : "l"(Bptr));

    float acc[4][4][4];
    #pragma unroll
    for (int a = 0; a < 4; a++)
        #pragma unroll
        for (int b = 0; b < 4; b++)
            #pragma unroll
            for (int c = 0; c < 4; c++) acc[a][b][c] = 0.f;

    #pragma unroll
    for (int i = 0; i < 2; i++) {
        uint32_t st = sb + i * STAGE_BYTES;
        uint64_t off = (uint64_t)i * (KC * 2);
        #pragma unroll
        for (int r = 0; r < 4; r++) {
            cpa(st + dstT[r],           gA + off + srcT[r]);
            cpa(st + A_BYTES + dstT[r], gB + off + srcT[r]);
        }
        asm volatile("cp.async.commit_group;" ::: "memory");
    }

    const int arow = lane & 15;
    const int ahi  = (lane >> 4) & 1;
    const int bcol = wn * 32 + (lane & 7) + (((lane >> 4) & 1) << 3);
    const int bhi  = (lane >> 3) & 1;

    int s = 0;
    for (int i = 0; i < NCHv; i++) {
        if (i < NCHv - 1)
            asm volatile("cp.async.wait_group 1;" ::: "memory");
        else
            asm volatile("cp.async.wait_group 0;" ::: "memory");
        __syncthreads();

        const uint32_t st = sb + s * STAGE_BYTES;
        const uint32_t aBase = st + wm * (64 * 128);
        const uint32_t bBase = st + A_BYTES;
        #pragma unroll
        for (int ks = 0; ks < 4; ks++) {
            uint32_t bf[2][4];
            #pragma unroll
            for (int nt2 = 0; nt2 < 2; nt2++) {
                int col = bcol + nt2 * 16;
                int kg = ks * 2 + bhi;
                ldsm4(bf[nt2], bBase + col * 128 + ((kg ^ (col & 7)) << 4));
            }
            #pragma unroll
            for (int mt = 0; mt < 4; mt++) {
                int row = mt * 16 + arow;
                int kg = ks * 2 + ahi;
                uint32_t af[4];
                ldsm4(af, aBase + row * 128 + ((kg ^ (row & 7)) << 4));
                #pragma unroll
                for (int nt = 0; nt < 4; nt++)
                    mma16(acc[mt][nt], af, &bf[nt >> 1][(nt & 1) * 2]);
            }
        }

        if (i + 2 < NCHv) {
            int s2 = s + 2; if (s2 >= STAGES) s2 -= STAGES;
            uint32_t st2 = sb + s2 * STAGE_BYTES;
            uint64_t off = (uint64_t)(i + 2) * (KC * 2);
            #pragma unroll
            for (int r = 0; r < 4; r++) {
                cpa(st2 + dstT[r],           gA + off + srcT[r]);
                cpa(st2 + A_BYTES + dstT[r], gB + off + srcT[r]);
            }
            asm volatile("cp.async.commit_group;" ::: "memory");
        }
        s++; if (s == STAGES) s = 0;
    }

    // ---- epilogue: smem transpose, coalesced row stores + mirror ----
    __syncthreads();
    float* stile = (float*)smem;          // 128 x 132 floats
    #pragma unroll
    for (int mt = 0; mt < 4; mt++) {
        #pragma unroll
        for (int nt = 0; nt < 4; nt++) {
            #pragma unroll
            for (int p = 0; p < 2; p++) {
                int row = wm * 64 + mt * 16 + (lane >> 2);
                int c   = wn * 32 + nt * 8 + (lane & 3) * 2 + p;
                stile[row * 132 + c]       = acc[mt][nt][p];
                stile[(row + 8) * 132 + c] = acc[mt][nt][2 + p];
            }
        }
    }
    __syncthreads();

    const size_t TOT = (size_t)BATCH * NFFT * FRAMES;
    const int c = tid & 127;
    const int g = ct * NT2 + c;
    if (g < NCOLS) {
        const int b = g / FRAMES;
        const int t = g - b * FRAMES;
        const size_t cb = (size_t)b * ((size_t)NFFT * FRAMES) + t;
        #pragma unroll 8
        for (int r0 = 0; r0 < 128; r0 += 2) {
            int row = r0 + (tid >> 7);
            int k = kbase + kstep * row;
            float v = stile[row * 132 + c];
            if (!is_imag) {
                out[cb + (size_t)k * FRAMES] = v;
                if (k >= 1) out[cb + (size_t)(NFFT - k) * FRAMES] = v;
            } else {
                out[TOT + cb + (size_t)k * FRAMES] = -v;
                if (k >= 1) out[TOT + cb + (size_t)(NFFT - k) * FRAMES] = v;
            }
        }
    }
}

extern "C" void kernel_launch(void* const* d_in, const int* in_sizes, int n_in,
                              void* d_out, int out_size) {
    const float* x = (const float*)d_in[0];
    float* out = (float*)d_out;

    cudaFuncSetAttribute(stft_mma7, cudaFuncAttributeMaxDynamicSharedMemorySize, SMEM_TOTAL);

    prep_all<<<NPAD + WBLOCKS, 256>>>(x, out);
    stft_mma7<<<dim3(NPAD / NT2, 16), 256, SMEM_TOTAL>>>(out);
}

// round 15
// speedup vs baseline: 1.0263x; 1.0263x over previous
#include <cuda_runtime.h>
#include <cuda_fp16.h>
#include <cstdint>

#define LENGTH   262144
#define NFFT     2048
#define HOP      512
#define BATCH    16
#define FRAMES   513
#define NCOLS    (BATCH * FRAMES)      // 8208
#define NPAD     8448                  // 66 * 128
#define KPE      320                   // even phases: 257 live + pad (5 chunks)
#define KPO      576                   // odd phases: 513 live + pad (9 chunks)
#define NCHE     5
#define NCHO     9
#define KC       64
#define MT2      128
#define NT2      128
#define A_BYTES  (MT2 * 128)
#define B_BYTES  (NT2 * 128)
#define STAGE_BYTES (A_BYTES + B_BYTES) // 32768
#define STAGES   3
#define SMEM_TOTAL (STAGES * STAGE_BYTES) // 98304
#define NW_E     (4 * 256 * KPE)       // 327680
#define NW_O     (2 * 512 * KPO)       // 589824
#define WBLOCKS  ((NW_E + NW_O) / 256) // 3584

// even B phases: 0=Pe2p (k=4m), 1=Pe2m (k=4m+2), 2=Me2m (k=4m), 3=Me2p (k=4m+2)
__device__ __align__(16) __half g_We[NW_E];
__device__ __align__(16) __half g_Wo[NW_O];
__device__ __align__(16) __half g_Be[4 * NPAD * KPE];   // 21.6 MB
__device__ __align__(16) __half g_Bo[2 * NPAD * KPO];   // 19.5 MB

__device__ __forceinline__ uint32_t smem_u32(const void* p) {
    uint32_t a;
    asm("{ .reg .u64 t; cvta.to.shared.u64 t, %1; cvt.u32.u64 %0, t; }" : "=r"(a) : "l"(p));
    return a;
}
__device__ __forceinline__ void cpa(uint32_t dst, uint64_t gsrc) {
    asm volatile("cp.async.cg.shared.global [%0], [%1], 16;" :: "r"(dst), "l"(gsrc) : "memory");
}
__device__ __forceinline__ void ldsm4(uint32_t* r, uint32_t a) {
    asm volatile("ldmatrix.sync.aligned.m8n8.x4.shared.b16 {%0,%1,%2,%3}, [%4];"
        : "=r"(r[0]), "=r"(r[1]), "=r"(r[2]), "=r"(r[3]) : "r"(a));
}
__device__ __forceinline__ void mma16(float* c, const uint32_t* a, const uint32_t* b) {
    asm volatile("mma.sync.aligned.m16n8k16.row.col.f32.f16.f16.f32 "
        "{%0,%1,%2,%3}, {%4,%5,%6,%7}, {%8,%9}, {%0,%1,%2,%3};"
        : "+f"(c[0]), "+f"(c[1]), "+f"(c[2]), "+f"(c[3])
        : "r"(a[0]), "r"(a[1]), "r"(a[2]), "r"(a[3]), "r"(b[0]), "r"(b[1]));
}
__device__ __forceinline__ float xrefl(const float* xb, int i) {
    if (i < 0) i = -i;
    else if (i >= LENGTH) i = 2 * LENGTH - 2 - i;
    return xb[i];
}
__device__ __forceinline__ void stcs(float* p, float v) {
    asm volatile("st.global.cs.f32 [%0], %1;" :: "l"(p), "f"(v) : "memory");
}

// ---- fused prep: blocks [0, NPAD) build B (single pass); rest build W ----
__global__ __launch_bounds__(256) void prep_all(const float* __restrict__ x,
                                                float* __restrict__ out)
{
    const int tid = threadIdx.x;

    if (blockIdx.x >= NPAD) {
        // ---------- W builder ----------
        int idx = (blockIdx.x - NPAD) * 256 + tid;
        if (idx < NW_E) {
            int p = idx / (256 * KPE);
            int r = idx - p * (256 * KPE);
            int m = r / KPE;
            int n = r - m * KPE;
            float v = 0.f;
            if (n <= 256) {
                if (p == 0)      v = cospif((float)(m * n) / 256.0f);
                else if (p == 1) v = cospif((float)((2 * m + 1) * n) / 512.0f);
                else if (p == 2) v = sinpif((float)(m * n) / 256.0f);
                else             v = sinpif((float)((2 * m + 1) * n) / 512.0f);
            }
            g_We[idx] = __float2half_rn(v);
        } else {
            int r = idx - NW_E;
            if (r < NW_O) {
                int p = r / (512 * KPO);
                int q = r - p * (512 * KPO);
                int m = q / KPO;
                int n = q - m * KPO;
                float v = 0.f;
                if (n <= 512) {
                    float u = (float)((2 * m + 1) * n) / 1024.0f;
                    v = p ? sinpif(u) : cospif(u);
                }
                g_Wo[r] = __float2half_rn(v);
            }
        }
        return;
    }

    // ---------- B builder: one column per block, single fused pass ----------
    __shared__ __align__(16) float xs[2052];
    __shared__ float red[8];
    const int col = blockIdx.x;

    __half* be0 = g_Be + 0 * (size_t)NPAD * KPE + (size_t)col * KPE;
    __half* be1 = g_Be + 1 * (size_t)NPAD * KPE + (size_t)col * KPE;
    __half* be2 = g_Be + 2 * (size_t)NPAD * KPE + (size_t)col * KPE;
    __half* be3 = g_Be + 3 * (size_t)NPAD * KPE + (size_t)col * KPE;
    __half* bo0 = g_Bo + 0 * (size_t)NPAD * KPO + (size_t)col * KPO;
    __half* bo1 = g_Bo + 1 * (size_t)NPAD * KPO + (size_t)col * KPO;

    if (col >= NCOLS) {
        __half z = __float2half_rn(0.f);
        for (int n = tid; n < KPE; n += 256) { be0[n] = z; be1[n] = z; be2[n] = z; be3[n] = z; }
        for (int j = tid; j < KPO; j += 256) { bo0[j] = z; bo1[j] = z; }
        return;
    }

    const int b = col / FRAMES;
    const int t = col - b * FRAMES;
    const float* __restrict__ xb = x + (size_t)b * LENGTH;
    const int base = t * HOP - 1024;

    for (int u = tid; u < 513; u += 256) {
        int gi = base + u * 4;
        float4 v;
        if (gi >= 0 && gi + 3 < LENGTH) {
            v = *(const float4*)(xb + gi);
        } else {
            float* vv = (float*)&v;
            #pragma unroll
            for (int e = 0; e < 4; e++) vv[e] = xrefl(xb, gi + e);
        }
        *(float4*)&xs[u * 4] = v;
    }
    __syncthreads();

    float alt = 0.f;
    for (int j = tid; j <= 256; j += 256) {        // tid 0 runs j=0 and j=256
        float u = (float)j / 1024.0f;
        float cj = cospif(u), sj = sinpif(u);
        float win_j   = 0.5f - 0.5f * cj;          // win(j)
        float win_cj  = 0.5f + 0.5f * cj;          // win(1024-j)
        float win_q   = 0.5f - 0.5f * sj;          // win(512-j)
        float win_cq  = 0.5f + 0.5f * sj;          // win(512+j)

        // fold at index j
        float xa = xs[j],        xd = xs[1024 + j];
        float x2 = xs[2048 - j], x1 = xs[1024 - j];
        float qa = win_j  * (xa + x2), qb = win_cj * (x1 + xd);
        float ma = win_j  * (xa - x2), mb = win_cj * (x1 - xd);
        float hj = (j == 0) ? 0.5f : 1.0f;
        float vpe_a = (qa + qb) * hj, vpo_a = (qa - qb) * hj;
        float vme_a = (ma - mb) * hj, vmo_a = (ma + mb) * hj;

        // fold at index jq = 512-j
        int jq = 512 - j;
        float ya = xs[jq],        yd = xs[1024 + jq];
        float y2 = xs[2048 - jq], y1 = xs[1024 - jq];
        float ra = win_q * (ya + y2), rb = win_cq * (y1 + yd);
        float na = win_q * (ya - y2), nb = win_cq * (y1 - yd);
        float hq = (jq == 512) ? 0.5f : 1.0f;
        float vpe_b = (ra + rb) * hq, vpo_b = (ra - rb) * hq;
        float vme_b = (na - nb) * hq, vmo_b = (na + nb) * hq;

        // odd-phase outputs
        bo0[j] = __float2half_rn(vpo_a);
        bo1[j] = __float2half_rn(vmo_a);
        if (j != jq) {
            bo0[jq] = __float2half_rn(vpo_b);
            bo1[jq] = __float2half_rn(vmo_b);
        }
        // even-phase second fold
        float h2 = (j == 256) ? 0.5f : 1.0f;
        be0[j] = __float2half_rn((vpe_a + vpe_b) * h2);
        be1[j] = __float2half_rn((vpe_a - vpe_b) * h2);
        be2[j] = __float2half_rn((vme_a - vme_b) * h2);
        be3[j] = __float2half_rn((vme_a + vme_b) * h2);
        // k=1024 row: sum (-1)^j vpe over 0..512 ; parity(jq) == parity(j)
        float contrib = vpe_a + ((j != jq) ? vpe_b : 0.f);
        alt += (j & 1) ? -contrib : contrib;
    }
    // zero padding tails
    for (int n = 257 + tid; n < KPE; n += 256) {
        __half z = __float2half_rn(0.f);
        be0[n] = z; be1[n] = z; be2[n] = z; be3[n] = z;
    }
    for (int j2 = 513 + tid; j2 < KPO; j2 += 256) {
        __half z = __float2half_rn(0.f);
        bo0[j2] = z; bo1[j2] = z;
    }

    #pragma unroll
    for (int off = 16; off > 0; off >>= 1)
        alt += __shfl_down_sync(0xFFFFFFFF, alt, off);
    if ((tid & 31) == 0) red[tid >> 5] = alt;
    __syncthreads();
    if (tid == 0) {
        float s = 0.f;
        #pragma unroll
        for (int w = 0; w < 8; w++) s += red[w];
        const size_t TOT = (size_t)BATCH * NFFT * FRAMES;
        size_t o = ((size_t)b * NFFT + 1024) * FRAMES + t;
        stcs(out + o, s);
        stcs(out + TOT + o, 0.f);
    }
}

// ---- unified GEMM: grid (66, 16); ty<8 even tiles (K=320), ty>=8 odd (K=576) ----
__global__ __launch_bounds__(256, 2) void stft_mma8(float* __restrict__ out)
{
    extern __shared__ __align__(128) char smem[];
    const uint32_t sb = smem_u32(smem);
    const int tid  = threadIdx.x;
    const int lane = tid & 31;
    const int wid  = tid >> 5;
    const int ct = blockIdx.x;
    const int ty = blockIdx.y;
    const int wm = wid & 1;
    const int wn = wid >> 1;

    int KP, NCHv, kbase, kstep;
    bool is_imag;
    const __half *Aptr, *Bptr;
    if (ty < 8) {
        int pe  = ty >> 1;
        int mr0 = (ty & 1) * 128;
        KP = KPE; NCHv = NCHE;
        Aptr = g_We + ((size_t)pe * 256 + mr0) * KPE;
        Bptr = g_Be + ((size_t)pe * NPAD + (size_t)ct * NT2) * KPE;
        is_imag = (pe >= 2);
        kbase = 4 * mr0 + ((pe & 1) ? 2 : 0);
        kstep = 4;
    } else {
        int po  = (ty - 8) >> 2;
        int mr0 = ((ty - 8) & 3) * 128;
        KP = KPO; NCHv = NCHO;
        Aptr = g_Wo + ((size_t)po * 512 + mr0) * KPO;
        Bptr = g_Bo + ((size_t)po * NPAD + (size_t)ct * NT2) * KPO;
        is_imag = (po == 1);
        kbase = 2 * mr0 + 1;
        kstep = 2;
    }

    uint32_t dstT[4]; uint64_t srcT[4];
    #pragma unroll
    for (int r = 0; r < 4; r++) {
        int idx = tid + r * 256;
        int row = idx >> 3, kg = idx & 7;
        dstT[r] = (uint32_t)(row * 128 + ((kg ^ (row & 7)) << 4));
        srcT[r] = (uint64_t)row * (KP * 2) + (uint64_t)kg * 16;
    }
    uint64_t gA, gB;
    asm("cvta.to.global.u64 %0, %1;" : "=l"(gA) : "l"(Aptr));
    asm("cvta.to.global.u64 %0, %1;" : "=l"(gB) : "l"(Bptr));

    float acc[4][4][4];
    #pragma unroll
    for (int a = 0; a < 4; a++)
        #pragma unroll
        for (int b = 0; b < 4; b++)
            #pragma unroll
            for (int c = 0; c < 4; c++) acc[a][b][c] = 0.f;

    #pragma unroll
    for (int i = 0; i < 2; i++) {
        uint32_t st = sb + i * STAGE_BYTES;
        uint64_t off = (uint64_t)i * (KC * 2);
        #pragma unroll
        for (int r = 0; r < 4; r++) {
            cpa(st + dstT[r],           gA + off + srcT[r]);
            cpa(st + A_BYTES + dstT[r], gB + off + srcT[r]);
        }
        asm volatile("cp.async.commit_group;" ::: "memory");
    }

    const int arow = lane & 15;
    const int ahi  = (lane >> 4) & 1;
    const int bcol = wn * 32 + (lane & 7) + (((lane >> 4) & 1) << 3);
    const int bhi  = (lane >> 3) & 1;

    int s = 0;
    for (int i = 0; i < NCHv; i++) {
        if (i < NCHv - 1)
            asm volatile("cp.async.wait_group 1;" ::: "memory");
        else
            asm volatile("cp.async.wait_group 0;" ::: "memory");
        __syncthreads();

        const uint32_t st = sb + s * STAGE_BYTES;
        const uint32_t aBase = st + wm * (64 * 128);
        const uint32_t bBase = st + A_BYTES;
        #pragma unroll
        for (int ks = 0; ks < 4; ks++) {
            uint32_t bf[2][4];
            #pragma unroll
            for (int nt2 = 0; nt2 < 2; nt2++) {
                int col = bcol + nt2 * 16;
                int kg = ks * 2 + bhi;
                ldsm4(bf[nt2], bBase + col * 128 + ((kg ^ (col & 7)) << 4));
            }
            #pragma unroll
            for (int mt = 0; mt < 4; mt++) {
                int row = mt * 16 + arow;
                int kg = ks * 2 + ahi;
                uint32_t af[4];
                ldsm4(af, aBase + row * 128 + ((kg ^ (row & 7)) << 4));
                #pragma unroll
                for (int nt = 0; nt < 4; nt++)
                    mma16(acc[mt][nt], af, &bf[nt >> 1][(nt & 1) * 2]);
            }
        }

        if (i + 2 < NCHv) {
            int s2 = s + 2; if (s2 >= STAGES) s2 -= STAGES;
            uint32_t st2 = sb + s2 * STAGE_BYTES;
            uint64_t off = (uint64_t)(i + 2) * (KC * 2);
            #pragma unroll
            for (int r = 0; r < 4; r++) {
                cpa(st2 + dstT[r],           gA + off + srcT[r]);
                cpa(st2 + A_BYTES + dstT[r], gB + off + srcT[r]);
            }
            asm volatile("cp.async.commit_group;" ::: "memory");
        }
        s++; if (s == STAGES) s = 0;
    }

    // ---- epilogue: smem transpose, coalesced streaming row stores + mirror ----
    __syncthreads();
    float* stile = (float*)smem;          // 128 x 132 floats
    #pragma unroll
    for (int mt = 0; mt < 4; mt++) {
        #pragma unroll
        for (int nt = 0; nt < 4; nt++) {
            #pragma unroll
            for (int p = 0; p < 2; p++) {
                int row = wm * 64 + mt * 16 + (lane >> 2);
                int c   = wn * 32 + nt * 8 + (lane & 3) * 2 + p;
                stile[row * 132 + c]       = acc[mt][nt][p];
                stile[(row + 8) * 132 + c] = acc[mt][nt][2 + p];
            }
        }
    }
    __syncthreads();

    const size_t TOT = (size_t)BATCH * NFFT * FRAMES;
    const int c = tid & 127;
    const int g = ct * NT2 + c;
    if (g < NCOLS) {
        const int b = g / FRAMES;
        const int t = g - b * FRAMES;
        const size_t cb = (size_t)b * ((size_t)NFFT * FRAMES) + t;
        #pragma unroll 8
        for (int r0 = 0; r0 < 128; r0 += 2) {
            int row = r0 + (tid >> 7);
            int k = kbase + kstep * row;
            float v = stile[row * 132 + c];
            if (!is_imag) {
                stcs(out + cb + (size_t)k * FRAMES, v);
                if (k >= 1) stcs(out + cb + (size_t)(NFFT - k) * FRAMES, v);
            } else {
                stcs(out + TOT + cb + (size_t)k * FRAMES, -v);
                if (k >= 1) stcs(out + TOT + cb + (size_t)(NFFT - k) * FRAMES, v);
            }
        }
    }
}

extern "C" void kernel_launch(void* const* d_in, const int* in_sizes, int n_in,
                              void* d_out, int out_size) {
    const float* x = (const float*)d_in[0];
    float* out = (float*)d_out;

    cudaFuncSetAttribute(stft_mma8, cudaFuncAttributeMaxDynamicSharedMemorySize, SMEM_TOTAL);

    prep_all<<<NPAD + WBLOCKS, 256>>>(x, out);
    stft_mma8<<<dim3(NPAD / NT2, 16), 256, SMEM_TOTAL>>>(out);
}

// round 16
// speedup vs baseline: 1.0773x; 1.0496x over previous
#include <cuda_runtime.h>
#include <cuda_fp16.h>
#include <cstdint>

#define LENGTH   262144
#define NFFT     2048
#define HOP      512
#define BATCH    16
#define FRAMES   513
#define NCOLS    (BATCH * FRAMES)      // 8208
#define NPAD     8448                  // 66 * 128
#define KPE      320                   // even phases: 257 live + pad (5 chunks)
#define KPO      576                   // odd phases: 513 live + pad (9 chunks)
#define NCHE     5
#define NCHO     9
#define KC       64
#define MT2      128
#define NT2      128
#define A_BYTES  (MT2 * 128)
#define B_BYTES  (NT2 * 128)
#define STAGE_BYTES (A_BYTES + B_BYTES) // 32768
#define STAGES   3
#define SMEM_TOTAL (STAGES * STAGE_BYTES) // 98304
#define NW_E     (4 * 256 * KPE)       // 327680
#define NW_O     (2 * 512 * KPO)       // 589824
#define WBLOCKS  ((NW_E + NW_O) / 256) // 3584
#define QPB      129                   // 4-frame groups per batch (129*4 >= 513)
#define BBLK     (BATCH * QPB)         // 2064 B-builder blocks
#define PBLK     60                    // pad-zero blocks (240 pad cols / 4)

// even B phases: 0=Pe2p (k=4m), 1=Pe2m (k=4m+2), 2=Me2m (k=4m), 3=Me2p (k=4m+2)
__device__ __align__(16) __half g_We[NW_E];
__device__ __align__(16) __half g_Wo[NW_O];
__device__ __align__(16) __half g_Be[4 * NPAD * KPE];   // 21.6 MB
__device__ __align__(16) __half g_Bo[2 * NPAD * KPO];   // 19.5 MB

__device__ __forceinline__ uint32_t smem_u32(const void* p) {
    uint32_t a;
    asm("{ .reg .u64 t; cvta.to.shared.u64 t, %1; cvt.u32.u64 %0, t; }" : "=r"(a) : "l"(p));
    return a;
}
__device__ __forceinline__ void cpa(uint32_t dst, uint64_t gsrc) {
    asm volatile("cp.async.cg.shared.global [%0], [%1], 16;" :: "r"(dst), "l"(gsrc) : "memory");
}
__device__ __forceinline__ void ldsm4(uint32_t* r, uint32_t a) {
    asm volatile("ldmatrix.sync.aligned.m8n8.x4.shared.b16 {%0,%1,%2,%3}, [%4];"
        : "=r"(r[0]), "=r"(r[1]), "=r"(r[2]), "=r"(r[3]) : "r"(a));
}
__device__ __forceinline__ void mma16(float* c, const uint32_t* a, const uint32_t* b) {
    asm volatile("mma.sync.aligned.m16n8k16.row.col.f32.f16.f16.f32 "
        "{%0,%1,%2,%3}, {%4,%5,%6,%7}, {%8,%9}, {%0,%1,%2,%3};"
        : "+f"(c[0]), "+f"(c[1]), "+f"(c[2]), "+f"(c[3])
        : "r"(a[0]), "r"(a[1]), "r"(a[2]), "r"(a[3]), "r"(b[0]), "r"(b[1]));
}
__device__ __forceinline__ float xrefl(const float* xb, int i) {
    if (i < 0) i = -i;
    else if (i >= LENGTH) i = 2 * LENGTH - 2 - i;
    return xb[i];
}
__device__ __forceinline__ void stcs(float* p, float v) {
    asm volatile("st.global.cs.f32 [%0], %1;" :: "l"(p), "f"(v) : "memory");
}

// ---- fused prep ----
// blocks [0, BBLK): B builder, 4 frames per block (shared staging window)
// blocks [BBLK, BBLK+PBLK): zero pad columns
// blocks [BBLK+PBLK, ...): W builder
__global__ __launch_bounds__(256) void prep_all(const float* __restrict__ x,
                                                float* __restrict__ out)
{
    const int tid = threadIdx.x;

    if (blockIdx.x >= BBLK + PBLK) {
        // ---------- W builder ----------
        int idx = (blockIdx.x - BBLK - PBLK) * 256 + tid;
        if (idx < NW_E) {
            int p = idx / (256 * KPE);
            int r = idx - p * (256 * KPE);
            int m = r / KPE;
            int n = r - m * KPE;
            float v = 0.f;
            if (n <= 256) {
                if (p == 0)      v = cospif((float)(m * n) / 256.0f);
                else if (p == 1) v = cospif((float)((2 * m + 1) * n) / 512.0f);
                else if (p == 2) v = sinpif((float)(m * n) / 256.0f);
                else             v = sinpif((float)((2 * m + 1) * n) / 512.0f);
            }
            g_We[idx] = __float2half_rn(v);
        } else {
            int r = idx - NW_E;
            if (r < NW_O) {
                int p = r / (512 * KPO);
                int q = r - p * (512 * KPO);
                int m = q / KPO;
                int n = q - m * KPO;
                float v = 0.f;
                if (n <= 512) {
                    float u = (float)((2 * m + 1) * n) / 1024.0f;
                    v = p ? sinpif(u) : cospif(u);
                }
                g_Wo[r] = __float2half_rn(v);
            }
        }
        return;
    }

    if (blockIdx.x >= BBLK) {
        // ---------- pad-zero builder: 4 pad columns per block ----------
        int p = blockIdx.x - BBLK;
        __half z = __float2half_rn(0.f);
        #pragma unroll
        for (int cc = 0; cc < 4; cc++) {
            int col = NCOLS + p * 4 + cc;
            if (col >= NPAD) break;
            __half* be = g_Be + (size_t)col * KPE;
            __half* bo = g_Bo + (size_t)col * KPO;
            for (int n = tid; n < KPE; n += 256) {
                be[n] = z;
                be[(size_t)NPAD * KPE + n] = z;
                be[2 * (size_t)NPAD * KPE + n] = z;
                be[3 * (size_t)NPAD * KPE + n] = z;
            }
            for (int j = tid; j < KPO; j += 256) {
                bo[j] = z;
                bo[(size_t)NPAD * KPO + j] = z;
            }
        }
        return;
    }

    // ---------- B builder: 4 consecutive frames per block ----------
    __shared__ __align__(16) float xs[3592];
    __shared__ float red[8][4];
    const int bb = blockIdx.x / QPB;
    const int t0 = (blockIdx.x - bb * QPB) * 4;
    const float* __restrict__ xb = x + (size_t)bb * LENGTH;
    const int base = t0 * HOP - 1024;

    // stage x[base .. base+3584]
    for (int u = tid; u < 897; u += 256) {
        int gi = base + u * 4;
        float4 v;
        if (gi >= 0 && gi + 3 < LENGTH) {
            v = *(const float4*)(xb + gi);
        } else {
            float* vv = (float*)&v;
            #pragma unroll
            for (int e = 0; e < 4; e++) vv[e] = xrefl(xb, gi + e);
        }
        *(float4*)&xs[u * 4] = v;
    }
    __syncthreads();

    float altv[4] = {0.f, 0.f, 0.f, 0.f};
    #pragma unroll
    for (int cc = 0; cc < 4; cc++) {
        const int t = t0 + cc;
        if (t > 512) break;
        const int col = bb * FRAMES + t;
        const int off = cc * HOP;
        __half* be0 = g_Be + 0 * (size_t)NPAD * KPE + (size_t)col * KPE;
        __half* be1 = g_Be + 1 * (size_t)NPAD * KPE + (size_t)col * KPE;
        __half* be2 = g_Be + 2 * (size_t)NPAD * KPE + (size_t)col * KPE;
        __half* be3 = g_Be + 3 * (size_t)NPAD * KPE + (size_t)col * KPE;
        __half* bo0 = g_Bo + 0 * (size_t)NPAD * KPO + (size_t)col * KPO;
        __half* bo1 = g_Bo + 1 * (size_t)NPAD * KPO + (size_t)col * KPO;

        for (int j = tid; j <= 256; j += 256) {    // tid 0 runs j=0 and j=256
            float u = (float)j / 1024.0f;
            float cj = cospif(u), sj = sinpif(u);
            float win_j  = 0.5f - 0.5f * cj;       // win(j)
            float win_cj = 0.5f + 0.5f * cj;       // win(1024-j)
            float win_q  = 0.5f - 0.5f * sj;       // win(512-j)
            float win_cq = 0.5f + 0.5f * sj;       // win(512+j)

            float xa = xs[off + j],        xd = xs[off + 1024 + j];
            float x2 = xs[off + 2048 - j], x1 = xs[off + 1024 - j];
            float qa = win_j  * (xa + x2), qb = win_cj * (x1 + xd);
            float ma = win_j  * (xa - x2), mb = win_cj * (x1 - xd);
            float hj = (j == 0) ? 0.5f : 1.0f;
            float vpe_a = (qa + qb) * hj, vpo_a = (qa - qb) * hj;
            float vme_a = (ma - mb) * hj, vmo_a = (ma + mb) * hj;

            int jq = 512 - j;
            float ya = xs[off + jq],        yd = xs[off + 1024 + jq];
            float y2 = xs[off + 2048 - jq], y1 = xs[off + 1024 - jq];
            float ra = win_q * (ya + y2), rb = win_cq * (y1 + yd);
            float na = win_q * (ya - y2), nb = win_cq * (y1 - yd);
            float hq = (jq == 512) ? 0.5f : 1.0f;
            float vpe_b = (ra + rb) * hq, vpo_b = (ra - rb) * hq;
            float vme_b = (na - nb) * hq, vmo_b = (na + nb) * hq;

            bo0[j] = __float2half_rn(vpo_a);
            bo1[j] = __float2half_rn(vmo_a);
            if (j != jq) {
                bo0[jq] = __float2half_rn(vpo_b);
                bo1[jq] = __float2half_rn(vmo_b);
            }
            float h2 = (j == 256) ? 0.5f : 1.0f;
            be0[j] = __float2half_rn((vpe_a + vpe_b) * h2);
            be1[j] = __float2half_rn((vpe_a - vpe_b) * h2);
            be2[j] = __float2half_rn((vme_a - vme_b) * h2);
            be3[j] = __float2half_rn((vme_a + vme_b) * h2);
            float contrib = vpe_a + ((j != jq) ? vpe_b : 0.f);
            altv[cc] += (j & 1) ? -contrib : contrib;
        }
        // zero padding tails
        for (int n = 257 + tid; n < KPE; n += 256) {
            __half z = __float2half_rn(0.f);
            be0[n] = z; be1[n] = z; be2[n] = z; be3[n] = z;
        }
        for (int j2 = 513 + tid; j2 < KPO; j2 += 256) {
            __half z = __float2half_rn(0.f);
            bo0[j2] = z; bo1[j2] = z;
        }
    }

    // k=1024 rows for the 4 columns
    #pragma unroll
    for (int cc = 0; cc < 4; cc++) {
        float v = altv[cc];
        #pragma unroll
        for (int off = 16; off > 0; off >>= 1)
            v += __shfl_down_sync(0xFFFFFFFF, v, off);
        if ((tid & 31) == 0) red[tid >> 5][cc] = v;
    }
    __syncthreads();
    if (tid < 4) {
        int t = t0 + tid;
        if (t <= 512) {
            float s = 0.f;
            #pragma unroll
            for (int w = 0; w < 8; w++) s += red[w][tid];
            const size_t TOT = (size_t)BATCH * NFFT * FRAMES;
            size_t o = ((size_t)bb * NFFT + 1024) * FRAMES + t;
            stcs(out + o, s);
            stcs(out + TOT + o, 0.f);
        }
    }
}

// ---- unified GEMM (identical to R15): grid (66,16); ty<8 even (K=320), ty>=8 odd (K=576) ----
__global__ __launch_bounds__(256, 2) void stft_mma8(float* __restrict__ out)
{
    extern __shared__ __align__(128) char smem[];
    const uint32_t sb = smem_u32(smem);
    const int tid  = threadIdx.x;
    const int lane = tid & 31;
    const int wid  = tid >> 5;
    const int ct = blockIdx.x;
    const int ty = blockIdx.y;
    const int wm = wid & 1;
    const int wn = wid >> 1;

    int KP, NCHv, kbase, kstep;
    bool is_imag;
    const __half *Aptr, *Bptr;
    if (ty < 8) {
        int pe  = ty >> 1;
        int mr0 = (ty & 1) * 128;
        KP = KPE; NCHv = NCHE;
        Aptr = g_We + ((size_t)pe * 256 + mr0) * KPE;
        Bptr = g_Be + ((size_t)pe * NPAD + (size_t)ct * NT2) * KPE;
        is_imag = (pe >= 2);
        kbase = 4 * mr0 + ((pe & 1) ? 2 : 0);
        kstep = 4;
    } else {
        int po  = (ty - 8) >> 2;
        int mr0 = ((ty - 8) & 3) * 128;
        KP = KPO; NCHv = NCHO;
        Aptr = g_Wo + ((size_t)po * 512 + mr0) * KPO;
        Bptr = g_Bo + ((size_t)po * NPAD + (size_t)ct * NT2) * KPO;
        is_imag = (po == 1);
        kbase = 2 * mr0 + 1;
        kstep = 2;
    }

    uint32_t dstT[4]; uint64_t srcT[4];
    #pragma unroll
    for (int r = 0; r < 4; r++) {
        int idx = tid + r * 256;
        int row = idx >> 3, kg = idx & 7;
        dstT[r] = (uint32_t)(row * 128 + ((kg ^ (row & 7)) << 4));
        srcT[r] = (uint64_t)row * (KP * 2) + (uint64_t)kg * 16;
    }
    uint64_t gA, gB;
    asm("cvta.to.global.u64 %0, %1;" : "=l"(gA) : "l"(Aptr));
    asm("cvta.to.global.u64 %0, %1;" : "=l"(gB) : "l"(Bptr));

    float acc[4][4][4];
    #pragma unroll
    for (int a = 0; a < 4; a++)
        #pragma unroll
        for (int b = 0; b < 4; b++)
            #pragma unroll
            for (int c = 0; c < 4; c++) acc[a][b][c] = 0.f;

    #pragma unroll
    for (int i = 0; i < 2; i++) {
        uint32_t st = sb + i * STAGE_BYTES;
        uint64_t off = (uint64_t)i * (KC * 2);
        #pragma unroll
        for (int r = 0; r < 4; r++) {
            cpa(st + dstT[r],           gA + off + srcT[r]);
            cpa(st + A_BYTES + dstT[r], gB + off + srcT[r]);
        }
        asm volatile("cp.async.commit_group;" ::: "memory");
    }

    const int arow = lane & 15;
    const int ahi  = (lane >> 4) & 1;
    const int bcol = wn * 32 + (lane & 7) + (((lane >> 4) & 1) << 3);
    const int bhi  = (lane >> 3) & 1;

    int s = 0;
    for (int i = 0; i < NCHv; i++) {
        if (i < NCHv - 1)
            asm volatile("cp.async.wait_group 1;" ::: "memory");
        else
            asm volatile("cp.async.wait_group 0;" ::: "memory");
        __syncthreads();

        const uint32_t st = sb + s * STAGE_BYTES;
        const uint32_t aBase = st + wm * (64 * 128);
        const uint32_t bBase = st + A_BYTES;
        #pragma unroll
        for (int ks = 0; ks < 4; ks++) {
            uint32_t bf[2][4];
            #pragma unroll
            for (int nt2 = 0; nt2 < 2; nt2++) {
                int col = bcol + nt2 * 16;
                int kg = ks * 2 + bhi;
                ldsm4(bf[nt2], bBase + col * 128 + ((kg ^ (col & 7)) << 4));
            }
            #pragma unroll
            for (int mt = 0; mt < 4; mt++) {
                int row = mt * 16 + arow;
                int kg = ks * 2 + ahi;
                uint32_t af[4];
                ldsm4(af, aBase + row * 128 + ((kg ^ (row & 7)) << 4));
                #pragma unroll
                for (int nt = 0; nt < 4; nt++)
                    mma16(acc[mt][nt], af, &bf[nt >> 1][(nt & 1) * 2]);
            }
        }

        if (i + 2 < NCHv) {
            int s2 = s + 2; if (s2 >= STAGES) s2 -= STAGES;
            uint32_t st2 = sb + s2 * STAGE_BYTES;
            uint64_t off = (uint64_t)(i + 2) * (KC * 2);
            #pragma unroll
            for (int r = 0; r < 4; r++) {
                cpa(st2 + dstT[r],           gA + off + srcT[r]);
                cpa(st2 + A_BYTES + dstT[r], gB + off + srcT[r]);
            }
            asm volatile("cp.async.commit_group;" ::: "memory");
        }
        s++; if (s == STAGES) s = 0;
    }

    // ---- epilogue: smem transpose, coalesced streaming row stores + mirror ----
    __syncthreads();
    float* stile = (float*)smem;          // 128 x 132 floats
    #pragma unroll
    for (int mt = 0; mt < 4; mt++) {
        #pragma unroll
        for (int nt = 0; nt < 4; nt++) {
            #pragma unroll
            for (int p = 0; p < 2; p++) {
                int row = wm * 64 + mt * 16 + (lane >> 2);
                int c   = wn * 32 + nt * 8 + (lane & 3) * 2 + p;
                stile[row * 132 + c]       = acc[mt][nt][p];
                stile[(row + 8) * 132 + c] = acc[mt][nt][2 + p];
            }
        }
    }
    __syncthreads();

    const size_t TOT = (size_t)BATCH * NFFT * FRAMES;
    const int c = tid & 127;
    const int g = ct * NT2 + c;
    if (g < NCOLS) {
        const int b = g / FRAMES;
        const int t = g - b * FRAMES;
        const size_t cb = (size_t)b * ((size_t)NFFT * FRAMES) + t;
        #pragma unroll 8
        for (int r0 = 0; r0 < 128; r0 += 2) {
            int row = r0 + (tid >> 7);
            int k = kbase + kstep * row;
            float v = stile[row * 132 + c];
            if (!is_imag) {
                stcs(out + cb + (size_t)k * FRAMES, v);
                if (k >= 1) stcs(out + cb + (size_t)(NFFT - k) * FRAMES, v);
            } else {
                stcs(out + TOT + cb + (size_t)k * FRAMES, -v);
                if (k >= 1) stcs(out + TOT + cb + (size_t)(NFFT - k) * FRAMES, v);
            }
        }
    }
}

extern "C" void kernel_launch(void* const* d_in, const int* in_sizes, int n_in,
                              void* d_out, int out_size) {
    const float* x = (const float*)d_in[0];
    float* out = (float*)d_out;

    cudaFuncSetAttribute(stft_mma8, cudaFuncAttributeMaxDynamicSharedMemorySize, SMEM_TOTAL);

    prep_all<<<BBLK + PBLK + WBLOCKS, 256>>>(x, out);
    stft_mma8<<<dim3(NPAD / NT2, 16), 256, SMEM_TOTAL>>>(out);
}